// round 6
// baseline (speedup 1.0000x reference)
#include <cuda_runtime.h>

#define TT 512
#define BB 16384
#define HH 32
#define BLK 128
#define LPC 128           // lanes per CTA
#define AST 36            // floats per act row

typedef unsigned long long u64;

// ---- packed f32x2 helpers (PTX-only; ptxas never auto-fuses) ----
__device__ __forceinline__ u64 fma2(u64 a, u64 b, u64 c) {
    u64 d; asm("fma.rn.f32x2 %0,%1,%2,%3;" : "=l"(d) : "l"(a), "l"(b), "l"(c)); return d;
}
__device__ __forceinline__ u64 mul2(u64 a, u64 b) {
    u64 d; asm("mul.rn.f32x2 %0,%1,%2;" : "=l"(d) : "l"(a), "l"(b)); return d;
}
__device__ __forceinline__ u64 pack2(float lo, float hi) {
    u64 r; asm("mov.b64 %0,{%1,%2};" : "=l"(r) : "f"(lo), "f"(hi)); return r;
}
__device__ __forceinline__ u64 dup2(float x) { return pack2(x, x); }
__device__ __forceinline__ void unpack2(u64 v, float& lo, float& hi) {
    asm("mov.b64 {%0,%1},%2;" : "=f"(lo), "=f"(hi) : "l"(v));
}

// stable softplus + sigmoid sharing one exp
__device__ __forceinline__ void sp_sig(float z, float& sp, float& sg) {
    float u = __expf(-fabsf(z));
    float d = 1.0f + u;
    float r = __fdividef(1.0f, d);
    sp = fmaxf(z, 0.0f) + __logf(d);
    sg = (z >= 0.0f) ? r : 1.0f - r;
}
__device__ __forceinline__ float sigf(float z) {
    float u = __expf(-fabsf(z));
    float r = __fdividef(1.0f, 1.0f + u);
    return (z >= 0.0f) ? r : 1.0f - r;
}

__global__ void __launch_bounds__(BLK, 1) rnncell_pipe_kernel(
    const float* __restrict__ eps, const float* __restrict__ hs,
    const float* __restrict__ W1,  const float* __restrict__ b1,
    const float* __restrict__ W2,  const float* __restrict__ b2,
    const float* __restrict__ W3,  float* __restrict__ out)
{
    __shared__ __align__(16) float sW2 [HH * HH];
    __shared__ __align__(16) float sW2T[HH * HH];
    __shared__ __align__(16) float sAct[LPC * AST];

    const int tid = threadIdx.x;
    for (int i = tid; i < HH * HH; i += BLK) {
        float w = W2[i];
        sW2[i] = w;
        sW2T[(i & 31) * HH + (i >> 5)] = w;
    }
    __syncthreads();

    const int quarter = tid & 3;
    const int grp     = tid >> 2;
    const int co      = quarter * 8;
    const int gbase   = blockIdx.x * LPC + grp * 4;

    float* act[4];
    #pragma unroll
    for (int r = 0; r < 4; ++r) act[r] = sAct + (grp * 4 + r) * AST;

    u64 w1ap[4], w1bp[4], b1p[4], b2p[4];
    float w3s[8];
    #pragma unroll
    for (int j = 0; j < 4; ++j) {
        w1ap[j] = pack2(W1[co + 2*j],      W1[co + 2*j + 1]);
        w1bp[j] = pack2(W1[HH + co + 2*j], W1[HH + co + 2*j + 1]);
        b1p [j] = pack2(b1[co + 2*j],      b1[co + 2*j + 1]);
        b2p [j] = pack2(b2[co + 2*j],      b2[co + 2*j + 1]);
    }
    #pragma unroll
    for (int j = 0; j < 8; ++j) w3s[j] = W3[co + j];

    float gam[4], ec[4], hc[4];
    {
        float4 e4 = *(const float4*)(eps + gbase);
        float4 h4 = *(const float4*)(hs  + gbase);
        ec[0]=e4.x; ec[1]=e4.y; ec[2]=e4.z; ec[3]=e4.w;
        hc[0]=h4.x; hc[1]=h4.y; hc[2]=h4.z; hc[3]=h4.w;
        #pragma unroll
        for (int r = 0; r < 4; ++r) gam[r] = 0.0f;
    }

    u64 s1p[4][4], acc[4][4], tacc[4][4];
    float4 en4, hn4;

// ---- phase macros (lane index R or half base R0 compile-time) ----
#define PH_L1(R) do {                                                        \
    const u64 e2 = dup2(ec[R]);                                              \
    const u64 g2 = dup2(gam[R]);                                             \
    float a1v[8];                                                            \
    _Pragma("unroll")                                                        \
    for (int j = 0; j < 4; ++j) {                                            \
        u64 z = fma2(e2, w1ap[j], fma2(g2, w1bp[j], b1p[j]));                \
        float za, zb; unpack2(z, za, zb);                                    \
        float spa, sga, spb, sgb;                                            \
        sp_sig(za, spa, sga);                                                \
        sp_sig(zb, spb, sgb);                                                \
        a1v[2*j] = spa; a1v[2*j+1] = spb;                                    \
        s1p[R][j] = pack2(sga, sgb);                                         \
    }                                                                        \
    *(float4*)(act[R] + co)     = make_float4(a1v[0],a1v[1],a1v[2],a1v[3]);  \
    *(float4*)(act[R] + co + 4) = make_float4(a1v[4],a1v[5],a1v[6],a1v[7]);  \
} while (0)

#define PH_MV1(R0) do {                                                      \
    _Pragma("unroll")                                                        \
    for (int r = 0; r < 2; ++r)                                              \
        { acc[R0+r][0]=b2p[0]; acc[R0+r][1]=b2p[1];                          \
          acc[R0+r][2]=b2p[2]; acc[R0+r][3]=b2p[3]; }                        \
    _Pragma("unroll")                                                        \
    for (int q = 0; q < 4; ++q) {                                            \
        float av[2][8];                                                      \
        _Pragma("unroll")                                                    \
        for (int r = 0; r < 2; ++r) {                                        \
            float4 lo = *(const float4*)(act[R0+r] + q*8);                   \
            float4 hi = *(const float4*)(act[R0+r] + q*8 + 4);               \
            av[r][0]=lo.x; av[r][1]=lo.y; av[r][2]=lo.z; av[r][3]=lo.w;      \
            av[r][4]=hi.x; av[r][5]=hi.y; av[r][6]=hi.z; av[r][7]=hi.w;      \
        }                                                                    \
        _Pragma("unroll")                                                    \
        for (int kk = 0; kk < 8; ++kk) {                                     \
            const float* wr = sW2 + (q*8+kk)*HH + co;                        \
            ulonglong2 wlo = *(const ulonglong2*)wr;                         \
            ulonglong2 whi = *(const ulonglong2*)(wr + 4);                   \
            _Pragma("unroll")                                                \
            for (int r = 0; r < 2; ++r) {                                    \
                u64 ak = dup2(av[r][kk]);                                    \
                acc[R0+r][0] = fma2(ak, wlo.x, acc[R0+r][0]);                \
                acc[R0+r][1] = fma2(ak, wlo.y, acc[R0+r][1]);                \
                acc[R0+r][2] = fma2(ak, whi.x, acc[R0+r][2]);                \
                acc[R0+r][3] = fma2(ak, whi.y, acc[R0+r][3]);                \
            }                                                                \
        }                                                                    \
    }                                                                        \
} while (0)

#define PH_V2(R) do {                                                        \
    float v2v[8];                                                            \
    _Pragma("unroll")                                                        \
    for (int j = 0; j < 4; ++j) {                                            \
        float za, zb; unpack2(acc[R][j], za, zb);                            \
        v2v[2*j]   = sigf(za) * w3s[2*j];                                    \
        v2v[2*j+1] = sigf(zb) * w3s[2*j+1];                                  \
    }                                                                        \
    *(float4*)(act[R] + co)     = make_float4(v2v[0],v2v[1],v2v[2],v2v[3]);  \
    *(float4*)(act[R] + co + 4) = make_float4(v2v[4],v2v[5],v2v[6],v2v[7]);  \
} while (0)

#define PH_MV2(R0) do {                                                      \
    _Pragma("unroll")                                                        \
    for (int r = 0; r < 2; ++r)                                              \
        { tacc[R0+r][0]=0ull; tacc[R0+r][1]=0ull;                            \
          tacc[R0+r][2]=0ull; tacc[R0+r][3]=0ull; }                          \
    _Pragma("unroll")                                                        \
    for (int q = 0; q < 4; ++q) {                                            \
        float vv[2][8];                                                      \
        _Pragma("unroll")                                                    \
        for (int r = 0; r < 2; ++r) {                                        \
            float4 lo = *(const float4*)(act[R0+r] + q*8);                   \
            float4 hi = *(const float4*)(act[R0+r] + q*8 + 4);               \
            vv[r][0]=lo.x; vv[r][1]=lo.y; vv[r][2]=lo.z; vv[r][3]=lo.w;      \
            vv[r][4]=hi.x; vv[r][5]=hi.y; vv[r][6]=hi.z; vv[r][7]=hi.w;      \
        }                                                                    \
        _Pragma("unroll")                                                    \
        for (int kk = 0; kk < 8; ++kk) {                                     \
            const float* wr = sW2T + (q*8+kk)*HH + co;                       \
            ulonglong2 wlo = *(const ulonglong2*)wr;                         \
            ulonglong2 whi = *(const ulonglong2*)(wr + 4);                   \
            _Pragma("unroll")                                                \
            for (int r = 0; r < 2; ++r) {                                    \
                u64 vk = dup2(vv[r][kk]);                                    \
                tacc[R0+r][0] = fma2(vk, wlo.x, tacc[R0+r][0]);              \
                tacc[R0+r][1] = fma2(vk, wlo.y, tacc[R0+r][1]);              \
                tacc[R0+r][2] = fma2(vk, whi.x, tacc[R0+r][2]);              \
                tacc[R0+r][3] = fma2(vk, whi.y, tacc[R0+r][3]);              \
            }                                                                \
        }                                                                    \
    }                                                                        \
} while (0)

#define PH_EPI(R0, TE, EA, EB, HA, HB) do {                                  \
    float g0v[2], g1v[2];                                                    \
    _Pragma("unroll")                                                        \
    for (int r = 0; r < 2; ++r) {                                            \
        u64 g0p = 0ull, g1p = 0ull;                                          \
        _Pragma("unroll")                                                    \
        for (int j = 0; j < 4; ++j) {                                        \
            u64 v1 = mul2(s1p[R0+r][j], tacc[R0+r][j]);                      \
            g0p = fma2(v1, w1ap[j], g0p);                                    \
            g1p = fma2(v1, w1bp[j], g1p);                                    \
        }                                                                    \
        float a, b;                                                          \
        unpack2(g0p, a, b); g0v[r] = a + b;                                  \
        unpack2(g1p, a, b); g1v[r] = a + b;                                  \
    }                                                                        \
    _Pragma("unroll")                                                        \
    for (int r = 0; r < 2; ++r) {                                            \
        g0v[r] += __shfl_xor_sync(0xffffffffu, g0v[r], 1);                   \
        g0v[r] += __shfl_xor_sync(0xffffffffu, g0v[r], 2);                   \
        g1v[r] += __shfl_xor_sync(0xffffffffu, g1v[r], 1);                   \
        g1v[r] += __shfl_xor_sync(0xffffffffu, g1v[r], 2);                   \
    }                                                                        \
    if (quarter == 0)                                                        \
        *(float2*)(out + (size_t)(TE) * BB + gbase + (R0)) =                 \
            make_float2(g0v[0], g0v[1]);                                     \
    gam[R0]   = fmaf(hc[R0],   -g1v[0], gam[R0]);                            \
    gam[R0+1] = fmaf(hc[R0+1], -g1v[1], gam[R0+1]);                          \
    ec[R0] = (EA); ec[R0+1] = (EB);                                          \
    hc[R0] = (HA); hc[R0+1] = (HB);                                          \
} while (0)

    for (int t = 0; t < TT; ++t) {
        // ---- slot1: deferred Epi(h1, t-1)  +  L1(h0, t)  + prefetch ----
        if (t != 0) PH_EPI(2, t - 1, en4.z, en4.w, hn4.z, hn4.w);
        PH_L1(0);
        PH_L1(1);
        {
            const int tn = (t + 1 < TT) ? t + 1 : t;
            en4 = *(const float4*)(eps + (size_t)tn * BB + gbase);
            hn4 = *(const float4*)(hs  + (size_t)tn * BB + gbase);
        }
        __syncwarp();

        // ---- slot2: MV1(h0)  +  L1(h1) ----
        PH_MV1(0);
        PH_L1(2);
        PH_L1(3);
        __syncwarp();

        // ---- slot3: V2(h0)  +  MV1(h1) ----
        PH_V2(0);
        PH_V2(1);
        PH_MV1(2);
        __syncwarp();

        // ---- slot4: MV2(h0)  +  V2(h1) ----
        PH_MV2(0);
        PH_V2(2);
        PH_V2(3);
        __syncwarp();

        // ---- slot5: Epi(h0, t)  +  MV2(h1) ----
        PH_MV2(2);
        PH_EPI(0, t, en4.x, en4.y, hn4.x, hn4.y);
        __syncwarp();
    }
    // drain: Epi(h1, TT-1)
    PH_EPI(2, TT - 1, en4.z, en4.w, hn4.z, hn4.w);
}

extern "C" void kernel_launch(void* const* d_in, const int* in_sizes, int n_in,
                              void* d_out, int out_size) {
    const float* eps = (const float*)d_in[0];
    const float* hs  = (const float*)d_in[1];
    const float* W1  = (const float*)d_in[2];
    const float* b1  = (const float*)d_in[3];
    const float* W2  = (const float*)d_in[4];
    const float* b2  = (const float*)d_in[5];
    const float* W3  = (const float*)d_in[6];
    float* out = (float*)d_out;

    rnncell_pipe_kernel<<<BB / LPC, BLK>>>(eps, hs, W1, b1, W2, b2, W3, out);
}

// round 7
// speedup vs baseline: 1.5436x; 1.5436x over previous
#include <cuda_runtime.h>

#define TT 512
#define BB 16384
#define HH 32
#define RL 4              // batch lanes per thread
#define BLK 128
#define LPC 128           // lanes per CTA = (BLK/4) * RL
#define AST 36            // floats per act row (16B aligned; 36 ≡ 4 mod 32 banks)

typedef unsigned long long u64;

// ---- packed f32x2 helpers (PTX-only; ptxas never auto-fuses) ----
__device__ __forceinline__ u64 fma2(u64 a, u64 b, u64 c) {
    u64 d; asm("fma.rn.f32x2 %0,%1,%2,%3;" : "=l"(d) : "l"(a), "l"(b), "l"(c)); return d;
}
__device__ __forceinline__ u64 mul2(u64 a, u64 b) {
    u64 d; asm("mul.rn.f32x2 %0,%1,%2;" : "=l"(d) : "l"(a), "l"(b)); return d;
}
__device__ __forceinline__ u64 pack2(float lo, float hi) {
    u64 r; asm("mov.b64 %0,{%1,%2};" : "=l"(r) : "f"(lo), "f"(hi)); return r;
}
__device__ __forceinline__ u64 dup2(float x) { return pack2(x, x); }
__device__ __forceinline__ void unpack2(u64 v, float& lo, float& hi) {
    asm("mov.b64 {%0,%1},%2;" : "=f"(lo), "=f"(hi) : "l"(v));
}

// stable softplus + sigmoid sharing one exp
__device__ __forceinline__ void sp_sig(float z, float& sp, float& sg) {
    float u = __expf(-fabsf(z));
    float d = 1.0f + u;
    float r = __fdividef(1.0f, d);
    sp = fmaxf(z, 0.0f) + __logf(d);
    sg = (z >= 0.0f) ? r : 1.0f - r;
}
__device__ __forceinline__ float sigf(float z) {
    float u = __expf(-fabsf(z));
    float r = __fdividef(1.0f, 1.0f + u);
    return (z >= 0.0f) ? r : 1.0f - r;
}

__global__ void __launch_bounds__(BLK, 1) rnncell_r4f_kernel(
    const float* __restrict__ eps, const float* __restrict__ hs,
    const float* __restrict__ W1,  const float* __restrict__ b1,
    const float* __restrict__ W2,  const float* __restrict__ b2,
    const float* __restrict__ W3,  float* __restrict__ out)
{
    __shared__ __align__(16) float sW2 [HH * HH];     // W2[k][j]
    __shared__ __align__(16) float sW2T[HH * HH];     // W2T[j][k]
    __shared__ __align__(16) float sAct[LPC * AST];   // per-lane activation rows

    const int tid = threadIdx.x;
    for (int i = tid; i < HH * HH; i += BLK) {
        float w = W2[i];
        sW2[i] = w;
        sW2T[(i & 31) * HH + (i >> 5)] = w;
    }
    __syncthreads();

    const int quarter = tid & 3;      // 8-unit chunk I own
    const int grp     = tid >> 2;     // group 0..31
    const int co      = quarter * 8;

    // 4 consecutive gids per thread -> vector LDG/STG
    const int gbase = blockIdx.x * LPC + grp * RL;

    // act row for lane (grp,r) = grp + 32*r:
    //  - act loads (fixed q,r): 8 grp rows spaced 36 floats = banks 4g -> all
    //    distinct, 4-way quarter-broadcast => conflict-free, 1 wavefront.
    //  (old grp*4+r layout spaced same-r rows 144 floats = 16 mod 32 -> 4-way
    //   conflicts on every act access; that was R5's hidden cost.)
    float* act[RL];
    #pragma unroll
    for (int r = 0; r < RL; ++r) act[r] = sAct + (grp + 32 * r) * AST;

    // loop-invariant per-chunk weights
    u64 w1ap[4], w1bp[4], b1p[4], b2p[4];
    float w3s[8];
    #pragma unroll
    for (int j = 0; j < 4; ++j) {
        w1ap[j] = pack2(W1[co + 2*j],      W1[co + 2*j + 1]);
        w1bp[j] = pack2(W1[HH + co + 2*j], W1[HH + co + 2*j + 1]);
        b1p [j] = pack2(b1[co + 2*j],      b1[co + 2*j + 1]);
        b2p [j] = pack2(b2[co + 2*j],      b2[co + 2*j + 1]);
    }
    #pragma unroll
    for (int j = 0; j < 8; ++j) w3s[j] = W3[co + j];

    float gam[RL], ec[RL], hc[RL];
    {
        float4 e4 = *(const float4*)(eps + gbase);
        float4 h4 = *(const float4*)(hs  + gbase);
        ec[0]=e4.x; ec[1]=e4.y; ec[2]=e4.z; ec[3]=e4.w;
        hc[0]=h4.x; hc[1]=h4.y; hc[2]=h4.z; hc[3]=h4.w;
        #pragma unroll
        for (int r = 0; r < RL; ++r) gam[r] = 0.0f;
    }

    for (int t = 0; t < TT; ++t) {
        const int tn = (t + 1 < TT) ? t + 1 : t;
        float4 en4 = *(const float4*)(eps + (size_t)tn * BB + gbase);
        float4 hn4 = *(const float4*)(hs  + (size_t)tn * BB + gbase);

        // ---- layer 1 (my 8 units x 4 lanes): z1 -> softplus (staged), sigmoid (regs)
        u64 s1p[RL][4];
        #pragma unroll
        for (int r = 0; r < RL; ++r) {
            const u64 e2 = dup2(ec[r]);
            const u64 g2 = dup2(gam[r]);
            float a1v[8];
            #pragma unroll
            for (int j = 0; j < 4; ++j) {
                u64 z = fma2(e2, w1ap[j], fma2(g2, w1bp[j], b1p[j]));
                float za, zb; unpack2(z, za, zb);
                float spa, sga, spb, sgb;
                sp_sig(za, spa, sga);
                sp_sig(zb, spb, sgb);
                a1v[2*j]   = spa;
                a1v[2*j+1] = spb;
                s1p[r][j]  = pack2(sga, sgb);
            }
            *(float4*)(act[r] + co)     = make_float4(a1v[0], a1v[1], a1v[2], a1v[3]);
            *(float4*)(act[r] + co + 4) = make_float4(a1v[4], a1v[5], a1v[6], a1v[7]);
        }
        __syncwarp();

        // ---- matvec1: z2[my 8 cols] = b2 + sum_k a1[k] * W2[k][.] ----
        u64 acc[RL][4];
        #pragma unroll
        for (int r = 0; r < RL; ++r)
            #pragma unroll
            for (int j = 0; j < 4; ++j) acc[r][j] = b2p[j];

        #pragma unroll
        for (int q = 0; q < 4; ++q) {
            float av[RL][8];
            #pragma unroll
            for (int r = 0; r < RL; ++r) {
                float4 lo = *(const float4*)(act[r] + q * 8);
                float4 hi = *(const float4*)(act[r] + q * 8 + 4);
                av[r][0]=lo.x; av[r][1]=lo.y; av[r][2]=lo.z; av[r][3]=lo.w;
                av[r][4]=hi.x; av[r][5]=hi.y; av[r][6]=hi.z; av[r][7]=hi.w;
            }
            #pragma unroll
            for (int kk = 0; kk < 8; ++kk) {
                const float* wr = sW2 + (q * 8 + kk) * HH + co;
                ulonglong2 wlo = *(const ulonglong2*)wr;
                ulonglong2 whi = *(const ulonglong2*)(wr + 4);
                #pragma unroll
                for (int r = 0; r < RL; ++r) {
                    u64 ak = dup2(av[r][kk]);
                    acc[r][0] = fma2(ak, wlo.x, acc[r][0]);
                    acc[r][1] = fma2(ak, wlo.y, acc[r][1]);
                    acc[r][2] = fma2(ak, whi.x, acc[r][2]);
                    acc[r][3] = fma2(ak, whi.y, acc[r][3]);
                }
            }
        }
        __syncwarp();

        // ---- v2 = sigmoid(z2) * W3, staged ----
        #pragma unroll
        for (int r = 0; r < RL; ++r) {
            float v2v[8];
            #pragma unroll
            for (int j = 0; j < 4; ++j) {
                float za, zb; unpack2(acc[r][j], za, zb);
                v2v[2*j]   = sigf(za) * w3s[2*j];
                v2v[2*j+1] = sigf(zb) * w3s[2*j+1];
            }
            *(float4*)(act[r] + co)     = make_float4(v2v[0], v2v[1], v2v[2], v2v[3]);
            *(float4*)(act[r] + co + 4) = make_float4(v2v[4], v2v[5], v2v[6], v2v[7]);
        }
        __syncwarp();

        // ---- matvec2: t[my 8 rows] = sum_j v2[j] * W2T[j][.] ----
        u64 tacc[RL][4];
        #pragma unroll
        for (int r = 0; r < RL; ++r)
            #pragma unroll
            for (int j = 0; j < 4; ++j) tacc[r][j] = 0ull;

        #pragma unroll
        for (int q = 0; q < 4; ++q) {
            float vv[RL][8];
            #pragma unroll
            for (int r = 0; r < RL; ++r) {
                float4 lo = *(const float4*)(act[r] + q * 8);
                float4 hi = *(const float4*)(act[r] + q * 8 + 4);
                vv[r][0]=lo.x; vv[r][1]=lo.y; vv[r][2]=lo.z; vv[r][3]=lo.w;
                vv[r][4]=hi.x; vv[r][5]=hi.y; vv[r][6]=hi.z; vv[r][7]=hi.w;
            }
            #pragma unroll
            for (int kk = 0; kk < 8; ++kk) {
                const float* wr = sW2T + (q * 8 + kk) * HH + co;
                ulonglong2 wlo = *(const ulonglong2*)wr;
                ulonglong2 whi = *(const ulonglong2*)(wr + 4);
                #pragma unroll
                for (int r = 0; r < RL; ++r) {
                    u64 vk = dup2(vv[r][kk]);
                    tacc[r][0] = fma2(vk, wlo.x, tacc[r][0]);
                    tacc[r][1] = fma2(vk, wlo.y, tacc[r][1]);
                    tacc[r][2] = fma2(vk, whi.x, tacc[r][2]);
                    tacc[r][3] = fma2(vk, whi.y, tacc[r][3]);
                }
            }
        }
        __syncwarp();

        // ---- v1 = sig1 .* t ; partial dots ; 4-thread butterfly ----
        float g0[RL], g1[RL];
        #pragma unroll
        for (int r = 0; r < RL; ++r) {
            u64 g0p = 0ull, g1p = 0ull;
            #pragma unroll
            for (int j = 0; j < 4; ++j) {
                u64 v1 = mul2(s1p[r][j], tacc[r][j]);
                g0p = fma2(v1, w1ap[j], g0p);
                g1p = fma2(v1, w1bp[j], g1p);
            }
            float a, b;
            unpack2(g0p, a, b); g0[r] = a + b;
            unpack2(g1p, a, b); g1[r] = a + b;
        }
        #pragma unroll
        for (int r = 0; r < RL; ++r) {
            g0[r] += __shfl_xor_sync(0xffffffffu, g0[r], 1);
            g0[r] += __shfl_xor_sync(0xffffffffu, g0[r], 2);
            g1[r] += __shfl_xor_sync(0xffffffffu, g1[r], 1);
            g1[r] += __shfl_xor_sync(0xffffffffu, g1[r], 2);
        }

        if (quarter == 0)
            *(float4*)(out + (size_t)t * BB + gbase) =
                make_float4(g0[0], g0[1], g0[2], g0[3]);

        gam[0] = fmaf(hc[0], -g1[0], gam[0]);
        gam[1] = fmaf(hc[1], -g1[1], gam[1]);
        gam[2] = fmaf(hc[2], -g1[2], gam[2]);
        gam[3] = fmaf(hc[3], -g1[3], gam[3]);

        ec[0]=en4.x; ec[1]=en4.y; ec[2]=en4.z; ec[3]=en4.w;
        hc[0]=hn4.x; hc[1]=hn4.y; hc[2]=hn4.z; hc[3]=hn4.w;
    }
}

extern "C" void kernel_launch(void* const* d_in, const int* in_sizes, int n_in,
                              void* d_out, int out_size) {
    const float* eps = (const float*)d_in[0];
    const float* hs  = (const float*)d_in[1];
    const float* W1  = (const float*)d_in[2];
    const float* b1  = (const float*)d_in[3];
    const float* W2  = (const float*)d_in[4];
    const float* b2  = (const float*)d_in[5];
    const float* W3  = (const float*)d_in[6];
    float* out = (float*)d_out;

    // 16384 lanes / 128 per CTA = 128 CTAs x 128 threads
    rnncell_r4f_kernel<<<BB / LPC, BLK>>>(eps, hs, W1, b1, W2, b2, W3, out);
}